// round 10
// baseline (speedup 1.0000x reference)
#include <cuda_runtime.h>

#define B_SZ 16384
#define H    256
#define H3   768
#define NSTEP 50
#define PAD  36
#define BM   32
#define NTHR 512

// GRU persistent kernel config
#define NT2  256
#define BM2  16

typedef unsigned long long ull;

// Scratch: gz = zc@Wih[:260] + bih, and h (h0 in, h_final out for edge kernel).
__device__ __align__(16) float g_gz[B_SZ * H3];   // 48 MB
__device__ __align__(16) float g_hA[B_SZ * H];    // 16 MB

__device__ __forceinline__ ull dup2(float v) {
    ull r; asm("mov.b64 %0, {%1, %1};" : "=l"(r) : "f"(v)); return r;
}
__device__ __forceinline__ void ffma2(ull &acc, ull a, ull b) {
    asm("fma.rn.f32x2 %0, %1, %2, %0;" : "+l"(acc) : "l"(a), "l"(b));
}
__device__ __forceinline__ float2 unpk(ull v) {
    float2 r; asm("mov.b64 {%0, %1}, %2;" : "=f"(r.x), "=f"(r.y) : "l"(v)); return r;
}
__device__ __forceinline__ float sigf(float x) {
    return __fdividef(1.f, 1.f + __expf(-x));
}
__device__ __forceinline__ float tanhf_fast(float x) {
    return __fdividef(2.f, 1.f + __expf(-2.f * x)) - 1.f;
}

// ---------------------------------------------------------------------------
// Kernel 1: per-row precompute (unchanged from R9 pass).
//   gz  = zc @ Wih[0:260,:] + bih          -> g_gz   [B,768]
//   h0  = zc @ Wi + bi                     -> g_hA   [B,256]
//   nn  = relu(zc @ Wn1 + bn1) @ Wn2 + bn2 -> out0   [B,49]
// ---------------------------------------------------------------------------
__global__ void __launch_bounds__(NTHR) pre_kernel(
    const float* __restrict__ z,   const float* __restrict__ cond,
    const float* __restrict__ Wn1, const float* __restrict__ bn1,
    const float* __restrict__ Wn2, const float* __restrict__ bn2,
    const float* __restrict__ Wi,  const float* __restrict__ bi,
    const float* __restrict__ Wih, const float* __restrict__ bih,
    float* __restrict__ out0)
{
    extern __shared__ float smf[];
    float* zcT = smf;               // [260][PAD]
    float* nnT = zcT + 260 * PAD;   // [256][PAD]
    const int b0  = blockIdx.x * BM;
    const int tid = threadIdx.x;

    for (int idx = tid; idx < BM * 260; idx += NTHR) {
        int k = idx % 260, r = idx / 260;
        float v = (k < 256) ? z[(b0 + r) * 256 + k] : cond[(b0 + r) * 4 + (k - 256)];
        zcT[k * PAD + r] = v;
    }
    __syncthreads();

    const int jp = tid & 127, rg = tid >> 7;
    const int j0 = jp * 2, r0 = rg * 8;

    for (int pass = 0; pass < 5; ++pass) {
        const float* W; const float* bias; int ld, cb;
        if (pass < 3)       { W = Wih; bias = bih; ld = H3; cb = pass * 256; }
        else if (pass == 3) { W = Wi;  bias = bi;  ld = H;  cb = 0; }
        else                { W = Wn1; bias = bn1; ld = H;  cb = 0; }
        ull acc[4][2] = {};
        #pragma unroll 2
        for (int k = 0; k < 260; ++k) {
            float2 w = *(const float2*)(W + k * ld + cb + j0);
            ull w0 = dup2(w.x), w1 = dup2(w.y);
            const float* xr = zcT + k * PAD + r0;
            ull x01 = *(const ull*)(xr);
            ull x23 = *(const ull*)(xr + 2);
            ull x45 = *(const ull*)(xr + 4);
            ull x67 = *(const ull*)(xr + 6);
            ffma2(acc[0][0], x01, w0); ffma2(acc[0][1], x01, w1);
            ffma2(acc[1][0], x23, w0); ffma2(acc[1][1], x23, w1);
            ffma2(acc[2][0], x45, w0); ffma2(acc[2][1], x45, w1);
            ffma2(acc[3][0], x67, w0); ffma2(acc[3][1], x67, w1);
        }
        float bv0 = bias[cb + j0], bv1 = bias[cb + j0 + 1];
        #pragma unroll
        for (int p = 0; p < 4; ++p) {
            float2 a0 = unpk(acc[p][0]);
            float2 a1 = unpk(acc[p][1]);
            #pragma unroll
            for (int rr = 0; rr < 2; ++rr) {
                int r = r0 + 2 * p + rr;
                float v0 = (rr ? a0.y : a0.x) + bv0;
                float v1 = (rr ? a1.y : a1.x) + bv1;
                if (pass < 3) {
                    float2 o; o.x = v0; o.y = v1;
                    *(float2*)(g_gz + (b0 + r) * H3 + cb + j0) = o;
                } else if (pass == 3) {
                    float2 o; o.x = v0; o.y = v1;
                    *(float2*)(g_hA + (b0 + r) * H + j0) = o;
                } else {
                    nnT[(j0    ) * PAD + r] = fmaxf(v0, 0.f);
                    nnT[(j0 + 1) * PAD + r] = fmaxf(v1, 0.f);
                }
            }
        }
    }
    __syncthreads();

    for (int idx = tid; idx < BM * 49; idx += NTHR) {
        int row = idx / 49, o = idx % 49;
        float acc = bn2[o];
        #pragma unroll 8
        for (int k = 0; k < 256; ++k)
            acc = fmaf(nnT[k * PAD + row], Wn2[k * 49 + o], acc);
        out0[(b0 + row) * 49 + o] = acc;
    }
}

// ---------------------------------------------------------------------------
// Kernel 2: persistent GRU — each block owns 16 batch rows and runs ALL 50
// steps with h resident in shared memory (duplicated {h,h} float2 format so
// the FFMA2 a-operand is a direct LDS.128; W float2 is the b-operand, loaded
// directly as 64-bit — zero MOV overhead in the inner loop).
// Thread tile: 2 columns (packed in f32x2) x 8 rows x 3 gates = 24 ull accs.
// K=29 prev-loop runs first; its n-gate partial is stashed in smem so only
// 24 accumulators are ever live -> <=85 regs -> 3 blocks/SM (24 warps).
// ---------------------------------------------------------------------------
__global__ void __launch_bounds__(NT2, 3) gru_kernel(
    const float* __restrict__ target,
    const float* __restrict__ Wih, const float* __restrict__ Whh,
    const float* __restrict__ bhh,
    const float* __restrict__ Wt,  const float* __restrict__ bt,
    const float* __restrict__ Wp,  const float* __restrict__ bp,
    float* __restrict__ out1, float* __restrict__ out2)
{
    extern __shared__ float smf[];
    float* hd = smf;                    // [256][16] dup pairs -> 8192 floats (32KB)
    float* pd = hd + 256 * BM2 * 2;     // [32][16]  dup pairs -> 1024 floats (4KB)
    ull*   st = (ull*)(pd + 32 * BM2 * 2);  // [256 thr][8] ull stash (16KB)

    const int b0  = blockIdx.x * BM2;
    const int tid = threadIdx.x;
    const int jp  = tid & 127, rg = tid >> 7;
    const int j0  = jp * 2,    r0 = rg * 8;

    // load h0 (duplicated layout)
    for (int idx = tid; idx < 256 * BM2; idx += NT2) {
        int k = idx >> 4, r = idx & 15;
        float v = g_hA[(b0 + r) * 256 + k];
        hd[(k * 16 + r) * 2]     = v;
        hd[(k * 16 + r) * 2 + 1] = v;
    }

    float2 bhr = *(const float2*)(bhh + j0);
    float2 bhz = *(const float2*)(bhh + 256 + j0);
    float2 bhn = *(const float2*)(bhh + 512 + j0);
    ull* stp = st + tid * 8;

    for (int t = 0; t < NSTEP; ++t) {
        // fill prev-feature dup tile for this step
        for (int idx = tid; idx < 32 * BM2; idx += NT2) {
            int kp = idx >> 4, r = idx & 15;
            float v = 0.f;
            if (t > 0 && kp < 29) v = target[((b0 + r) * NSTEP + (t - 1)) * 29 + kp];
            pd[(kp * 16 + r) * 2]     = v;
            pd[(kp * 16 + r) * 2 + 1] = v;
        }
        __syncthreads();   // pd ready; hd stable from previous step

        ull aR[8] = {}, aZ[8] = {}, aN[8] = {};

        // K=29 prev part: r,z add directly; n-input part goes to aN then stash
        #pragma unroll 1
        for (int kp = 0; kp < 29; ++kp) {
            const float* wb = Wih + (260 + kp) * H3 + j0;
            ull wr = *(const ull*)(wb);
            ull wz = *(const ull*)(wb + 256);
            ull wn = *(const ull*)(wb + 512);
            const ulonglong2* hp = (const ulonglong2*)(pd + (kp * 16 + r0) * 2);
            ulonglong2 hA = hp[0], hB = hp[1], hC = hp[2], hD = hp[3];
            ffma2(aR[0], hA.x, wr); ffma2(aR[1], hA.y, wr);
            ffma2(aR[2], hB.x, wr); ffma2(aR[3], hB.y, wr);
            ffma2(aR[4], hC.x, wr); ffma2(aR[5], hC.y, wr);
            ffma2(aR[6], hD.x, wr); ffma2(aR[7], hD.y, wr);
            ffma2(aZ[0], hA.x, wz); ffma2(aZ[1], hA.y, wz);
            ffma2(aZ[2], hB.x, wz); ffma2(aZ[3], hB.y, wz);
            ffma2(aZ[4], hC.x, wz); ffma2(aZ[5], hC.y, wz);
            ffma2(aZ[6], hD.x, wz); ffma2(aZ[7], hD.y, wz);
            ffma2(aN[0], hA.x, wn); ffma2(aN[1], hA.y, wn);
            ffma2(aN[2], hB.x, wn); ffma2(aN[3], hB.y, wn);
            ffma2(aN[4], hC.x, wn); ffma2(aN[5], hC.y, wn);
            ffma2(aN[6], hD.x, wn); ffma2(aN[7], hD.y, wn);
        }
        #pragma unroll
        for (int i = 0; i < 8; ++i) { stp[i] = aN[i]; aN[i] = 0; }

        // main K=256 recurrent GEMM: aR/aZ/aN(=Nh) over Whh
        #pragma unroll 2
        for (int k = 0; k < 256; ++k) {
            const float* wb = Whh + k * H3 + j0;
            ull wr = *(const ull*)(wb);
            ull wz = *(const ull*)(wb + 256);
            ull wn = *(const ull*)(wb + 512);
            const ulonglong2* hp = (const ulonglong2*)(hd + (k * 16 + r0) * 2);
            ulonglong2 hA = hp[0], hB = hp[1], hC = hp[2], hD = hp[3];
            ffma2(aR[0], hA.x, wr); ffma2(aR[1], hA.y, wr);
            ffma2(aR[2], hB.x, wr); ffma2(aR[3], hB.y, wr);
            ffma2(aR[4], hC.x, wr); ffma2(aR[5], hC.y, wr);
            ffma2(aR[6], hD.x, wr); ffma2(aR[7], hD.y, wr);
            ffma2(aZ[0], hA.x, wz); ffma2(aZ[1], hA.y, wz);
            ffma2(aZ[2], hB.x, wz); ffma2(aZ[3], hB.y, wz);
            ffma2(aZ[4], hC.x, wz); ffma2(aZ[5], hC.y, wz);
            ffma2(aZ[6], hD.x, wz); ffma2(aZ[7], hD.y, wz);
            ffma2(aN[0], hA.x, wn); ffma2(aN[1], hA.y, wn);
            ffma2(aN[2], hB.x, wn); ffma2(aN[3], hB.y, wn);
            ffma2(aN[4], hC.x, wn); ffma2(aN[5], hC.y, wn);
            ffma2(aN[6], hD.x, wn); ffma2(aN[7], hD.y, wn);
        }
        __syncthreads();   // all reads of hd complete before overwrite

        // gate math + in-place h update (each thread owns its (col,row) slots)
        #pragma unroll
        for (int i = 0; i < 8; ++i) {
            int r = r0 + i;
            const float* gzp = g_gz + (b0 + r) * H3 + j0;
            float2 gzr = *(const float2*)(gzp);
            float2 gzz = *(const float2*)(gzp + 256);
            float2 gzn = *(const float2*)(gzp + 512);
            float2 vR = unpk(aR[i]), vZ = unpk(aZ[i]), vN = unpk(aN[i]);
            float2 vI = unpk(stp[i]);
            float rg0 = sigf(vR.x + gzr.x + bhr.x);
            float rg1 = sigf(vR.y + gzr.y + bhr.y);
            float zg0 = sigf(vZ.x + gzz.x + bhz.x);
            float zg1 = sigf(vZ.y + gzz.y + bhz.y);
            float n0 = tanhf_fast(vI.x + gzn.x + rg0 * (vN.x + bhn.x));
            float n1 = tanhf_fast(vI.y + gzn.y + rg1 * (vN.y + bhn.y));
            float hold0 = hd[(j0 * 16 + r) * 2];
            float hold1 = hd[((j0 + 1) * 16 + r) * 2];
            float hn0 = n0 + zg0 * (hold0 - n0);
            float hn1 = n1 + zg1 * (hold1 - n1);
            hd[(j0 * 16 + r) * 2]           = hn0;
            hd[(j0 * 16 + r) * 2 + 1]       = hn0;
            hd[((j0 + 1) * 16 + r) * 2]     = hn1;
            hd[((j0 + 1) * 16 + r) * 2 + 1] = hn1;
            if (t == NSTEP - 1) {
                float2 o; o.x = hn0; o.y = hn1;
                *(float2*)(g_hA + (b0 + r) * H + j0) = o;
            }
        }
        __syncthreads();   // new h visible to all before heads read it

        // heads: 15 type logits + 14 sigmoid params per row
        for (int idx = tid; idx < BM2 * 29; idx += NT2) {
            int row = idx / 29, o = idx % 29;
            if (o < 15) {
                float acc = bt[o];
                #pragma unroll 8
                for (int k = 0; k < 256; ++k)
                    acc = fmaf(hd[(k * 16 + row) * 2], Wt[k * 15 + o], acc);
                out1[((b0 + row) * NSTEP + t) * 15 + o] = acc;
            } else {
                int oo = o - 15;
                float acc = bp[oo];
                #pragma unroll 8
                for (int k = 0; k < 256; ++k)
                    acc = fmaf(hd[(k * 16 + row) * 2], Wp[k * 14 + oo], acc);
                out2[((b0 + row) * NSTEP + t) * 14 + oo] = sigf(acc);
            }
        }
        // next iteration's pd-fill writes are fenced by the top __syncthreads
    }
}

// ---------------------------------------------------------------------------
// Kernel 3: edge head. Every ordered pair uses the SAME MLP([h,h,zc]) value,
// so compute one scalar per row and broadcast to all 2450 slots.
// ---------------------------------------------------------------------------
__global__ void __launch_bounds__(NTHR) edge_kernel(
    const float* __restrict__ z,   const float* __restrict__ cond,
    const float* __restrict__ We1, const float* __restrict__ be1,
    const float* __restrict__ We2, const float* __restrict__ be2,
    float* __restrict__ out3)
{
    extern __shared__ float smf[];
    float* xT  = smf;               // [516][PAD]  (h 0..255, zc 256..515)
    float* e1T = xT + 516 * PAD;    // [256][PAD]
    float* ev  = e1T + 256 * PAD;   // [32]
    const int b0  = blockIdx.x * BM;
    const int tid = threadIdx.x;

    for (int idx = tid; idx < BM * 516; idx += NTHR) {
        int k = idx % 516, r = idx / 516;
        float v = (k < 256) ? g_hA[(b0 + r) * 256 + k]
                : (k < 512) ? z[(b0 + r) * 256 + (k - 256)]
                            : cond[(b0 + r) * 4 + (k - 512)];
        xT[k * PAD + r] = v;
    }
    __syncthreads();

    const int jp = tid & 127, rg = tid >> 7;
    const int j0 = jp * 2, r0 = rg * 8;

    ull acc[4][2] = {};
    #pragma unroll 2
    for (int k = 0; k < 772; ++k) {
        int xrow = (k < 512) ? (k & 255) : (k - 256);
        float2 w = *(const float2*)(We1 + k * H + j0);
        ull w0 = dup2(w.x), w1 = dup2(w.y);
        const float* xr = xT + xrow * PAD + r0;
        ull x01 = *(const ull*)(xr);
        ull x23 = *(const ull*)(xr + 2);
        ull x45 = *(const ull*)(xr + 4);
        ull x67 = *(const ull*)(xr + 6);
        ffma2(acc[0][0], x01, w0); ffma2(acc[0][1], x01, w1);
        ffma2(acc[1][0], x23, w0); ffma2(acc[1][1], x23, w1);
        ffma2(acc[2][0], x45, w0); ffma2(acc[2][1], x45, w1);
        ffma2(acc[3][0], x67, w0); ffma2(acc[3][1], x67, w1);
    }
    float bv0 = be1[j0], bv1 = be1[j0 + 1];
    #pragma unroll
    for (int p = 0; p < 4; ++p) {
        float2 a0 = unpk(acc[p][0]), a1 = unpk(acc[p][1]);
        int r = r0 + 2 * p;
        e1T[(j0    ) * PAD + r    ] = fmaxf(a0.x + bv0, 0.f);
        e1T[(j0    ) * PAD + r + 1] = fmaxf(a0.y + bv0, 0.f);
        e1T[(j0 + 1) * PAD + r    ] = fmaxf(a1.x + bv1, 0.f);
        e1T[(j0 + 1) * PAD + r + 1] = fmaxf(a1.y + bv1, 0.f);
    }
    __syncthreads();

    if (tid < BM) {
        float a = be2[0];
        #pragma unroll 8
        for (int k = 0; k < 256; ++k)
            a = fmaf(e1T[k * PAD + tid], We2[k], a);
        ev[tid] = a;
    }
    __syncthreads();

    for (int idx = tid; idx < BM * 2450; idx += NTHR) {
        int row = idx / 2450, col = idx % 2450;
        out3[(b0 + row) * 2450 + col] = ev[row];
    }
}

// ---------------------------------------------------------------------------
extern "C" void kernel_launch(void* const* d_in, const int* in_sizes, int n_in,
                              void* d_out, int out_size)
{
    (void)in_sizes; (void)n_in; (void)out_size;
    const float* z    = (const float*)d_in[0];
    const float* cond = (const float*)d_in[1];
    const float* tgt  = (const float*)d_in[2];
    const float* Wn1  = (const float*)d_in[3];
    const float* bn1  = (const float*)d_in[4];
    const float* Wn2  = (const float*)d_in[5];
    const float* bn2  = (const float*)d_in[6];
    const float* Wi   = (const float*)d_in[7];
    const float* bi   = (const float*)d_in[8];
    const float* Wih  = (const float*)d_in[9];
    const float* Whh  = (const float*)d_in[10];
    const float* bih  = (const float*)d_in[11];
    const float* bhh  = (const float*)d_in[12];
    const float* Wt   = (const float*)d_in[13];
    const float* bt   = (const float*)d_in[14];
    const float* Wp   = (const float*)d_in[15];
    const float* bp   = (const float*)d_in[16];
    const float* We1  = (const float*)d_in[17];
    const float* be1  = (const float*)d_in[18];
    const float* We2  = (const float*)d_in[19];
    const float* be2  = (const float*)d_in[20];

    float* out  = (float*)d_out;
    float* out0 = out;                                  // [B, 49]
    float* out1 = out0 + (size_t)B_SZ * 49;             // [B, 50, 15]
    float* out2 = out1 + (size_t)B_SZ * NSTEP * 15;     // [B, 50, 14]
    float* out3 = out2 + (size_t)B_SZ * NSTEP * 14;     // [B, 2450]

    const int PRE_SMEM  = (260 + 256) * PAD * 4;                       // 74,304 B
    const int GRU_SMEM  = (256 * BM2 * 2 + 32 * BM2 * 2) * 4 + NT2 * 8 * 8;  // 53,248 B
    const int EDGE_SMEM = (516 + 256) * PAD * 4 + BM * 4;              // 111,296 B

    cudaFuncSetAttribute(pre_kernel,  cudaFuncAttributeMaxDynamicSharedMemorySize, PRE_SMEM);
    cudaFuncSetAttribute(gru_kernel,  cudaFuncAttributeMaxDynamicSharedMemorySize, GRU_SMEM);
    cudaFuncSetAttribute(edge_kernel, cudaFuncAttributeMaxDynamicSharedMemorySize, EDGE_SMEM);

    pre_kernel<<<B_SZ / BM, NTHR, PRE_SMEM>>>(z, cond, Wn1, bn1, Wn2, bn2, Wi, bi, Wih, bih, out0);
    gru_kernel<<<B_SZ / BM2, NT2, GRU_SMEM>>>(tgt, Wih, Whh, bhh, Wt, bt, Wp, bp, out1, out2);
    edge_kernel<<<B_SZ / BM, NTHR, EDGE_SMEM>>>(z, cond, We1, be1, We2, be2, out3);
}

// round 11
// speedup vs baseline: 1.4703x; 1.4703x over previous
#include <cuda_runtime.h>

#define B_SZ 16384
#define H    256
#define H3   768
#define NSTEP 50
#define PAD  36
#define BM   32
#define NTHR 512

// GRU persistent kernel config
#define NT2  256
#define BM2  16
#define HDP  18   // hd row stride (pad: keeps 8B alignment, 2-way conflicts max)

typedef unsigned long long ull;

// Scratch: gz = zc@Wih[:260] + bih, and h (h0 in, h_final out for edge kernel).
__device__ __align__(16) float g_gz[B_SZ * H3];   // 48 MB
__device__ __align__(16) float g_hA[B_SZ * H];    // 16 MB

__device__ __forceinline__ ull dup2(float v) {
    ull r; asm("mov.b64 %0, {%1, %1};" : "=l"(r) : "f"(v)); return r;
}
__device__ __forceinline__ void ffma2(ull &acc, ull a, ull b) {
    asm("fma.rn.f32x2 %0, %1, %2, %0;" : "+l"(acc) : "l"(a), "l"(b));
}
__device__ __forceinline__ float2 unpk(ull v) {
    float2 r; asm("mov.b64 {%0, %1}, %2;" : "=f"(r.x), "=f"(r.y) : "l"(v)); return r;
}
__device__ __forceinline__ float sigf(float x) {
    return __fdividef(1.f, 1.f + __expf(-x));
}
__device__ __forceinline__ float tanhf_fast(float x) {
    return __fdividef(2.f, 1.f + __expf(-2.f * x)) - 1.f;
}

// ---------------------------------------------------------------------------
// Kernel 1: per-row precompute (unchanged — passed R9/R10).
//   gz  = zc @ Wih[0:260,:] + bih          -> g_gz   [B,768]
//   h0  = zc @ Wi + bi                     -> g_hA   [B,256]
//   nn  = relu(zc @ Wn1 + bn1) @ Wn2 + bn2 -> out0   [B,49]
// ---------------------------------------------------------------------------
__global__ void __launch_bounds__(NTHR) pre_kernel(
    const float* __restrict__ z,   const float* __restrict__ cond,
    const float* __restrict__ Wn1, const float* __restrict__ bn1,
    const float* __restrict__ Wn2, const float* __restrict__ bn2,
    const float* __restrict__ Wi,  const float* __restrict__ bi,
    const float* __restrict__ Wih, const float* __restrict__ bih,
    float* __restrict__ out0)
{
    extern __shared__ float smf[];
    float* zcT = smf;               // [260][PAD]
    float* nnT = zcT + 260 * PAD;   // [256][PAD]
    const int b0  = blockIdx.x * BM;
    const int tid = threadIdx.x;

    for (int idx = tid; idx < BM * 260; idx += NTHR) {
        int k = idx % 260, r = idx / 260;
        float v = (k < 256) ? z[(b0 + r) * 256 + k] : cond[(b0 + r) * 4 + (k - 256)];
        zcT[k * PAD + r] = v;
    }
    __syncthreads();

    const int jp = tid & 127, rg = tid >> 7;
    const int j0 = jp * 2, r0 = rg * 8;

    for (int pass = 0; pass < 5; ++pass) {
        const float* W; const float* bias; int ld, cb;
        if (pass < 3)       { W = Wih; bias = bih; ld = H3; cb = pass * 256; }
        else if (pass == 3) { W = Wi;  bias = bi;  ld = H;  cb = 0; }
        else                { W = Wn1; bias = bn1; ld = H;  cb = 0; }
        ull acc[4][2] = {};
        #pragma unroll 2
        for (int k = 0; k < 260; ++k) {
            float2 w = *(const float2*)(W + k * ld + cb + j0);
            ull w0 = dup2(w.x), w1 = dup2(w.y);
            const float* xr = zcT + k * PAD + r0;
            ull x01 = *(const ull*)(xr);
            ull x23 = *(const ull*)(xr + 2);
            ull x45 = *(const ull*)(xr + 4);
            ull x67 = *(const ull*)(xr + 6);
            ffma2(acc[0][0], x01, w0); ffma2(acc[0][1], x01, w1);
            ffma2(acc[1][0], x23, w0); ffma2(acc[1][1], x23, w1);
            ffma2(acc[2][0], x45, w0); ffma2(acc[2][1], x45, w1);
            ffma2(acc[3][0], x67, w0); ffma2(acc[3][1], x67, w1);
        }
        float bv0 = bias[cb + j0], bv1 = bias[cb + j0 + 1];
        #pragma unroll
        for (int p = 0; p < 4; ++p) {
            float2 a0 = unpk(acc[p][0]);
            float2 a1 = unpk(acc[p][1]);
            #pragma unroll
            for (int rr = 0; rr < 2; ++rr) {
                int r = r0 + 2 * p + rr;
                float v0 = (rr ? a0.y : a0.x) + bv0;
                float v1 = (rr ? a1.y : a1.x) + bv1;
                if (pass < 3) {
                    float2 o; o.x = v0; o.y = v1;
                    *(float2*)(g_gz + (b0 + r) * H3 + cb + j0) = o;
                } else if (pass == 3) {
                    float2 o; o.x = v0; o.y = v1;
                    *(float2*)(g_hA + (b0 + r) * H + j0) = o;
                } else {
                    nnT[(j0    ) * PAD + r] = fmaxf(v0, 0.f);
                    nnT[(j0 + 1) * PAD + r] = fmaxf(v1, 0.f);
                }
            }
        }
    }
    __syncthreads();

    for (int idx = tid; idx < BM * 49; idx += NTHR) {
        int row = idx / 49, o = idx % 49;
        float acc = bn2[o];
        #pragma unroll 8
        for (int k = 0; k < 256; ++k)
            acc = fmaf(nnT[k * PAD + row], Wn2[k * 49 + o], acc);
        out0[(b0 + row) * 49 + o] = acc;
    }
}

// ---------------------------------------------------------------------------
// Kernel 2: persistent GRU, column-per-thread tiling.
// Thread j owns output column j for ALL 16 batch rows of its block:
//   - each Whh value is loaded exactly ONCE per block per k (no rg redundancy)
//   - W loads are 3 scalar __ldcg (L2-only, keeps L1 clean), dup'd into the
//     FFMA2 b-operand; depth-2 register prefetch pipeline hides L2 latency
//   - h operand = natural {h[r],h[r+1]} pairs from broadcast LDS.64
// Accumulators: 3 gates x 8 row-pairs = 24 ull (48 regs).
// K=29 prev-feature pass runs first; its n-gate partial stashes to smem.
// ---------------------------------------------------------------------------
__global__ void __launch_bounds__(NT2, 3) gru_kernel(
    const float* __restrict__ target,
    const float* __restrict__ Wih, const float* __restrict__ Whh,
    const float* __restrict__ bhh,
    const float* __restrict__ Wt,  const float* __restrict__ bt,
    const float* __restrict__ Wp,  const float* __restrict__ bp,
    float* __restrict__ out1, float* __restrict__ out2)
{
    __shared__ __align__(16) float hd[256 * HDP];   // 18,432 B
    __shared__ __align__(16) float pd[32 * HDP];    //  2,304 B
    __shared__ __align__(16) ull   st[256 * 8];     // 16,384 B

    const int b0 = blockIdx.x * BM2;
    const int j  = threadIdx.x;          // output column 0..255

    // load h0: hd[k*HDP + r] = g_hA[(b0+r)*256 + k]
    for (int idx = j; idx < 256 * BM2; idx += NT2) {
        int k = idx >> 4, r = idx & 15;
        hd[k * HDP + r] = g_hA[(b0 + r) * 256 + k];
    }

    const float bhr = bhh[j], bhz = bhh[256 + j], bhn = bhh[512 + j];
    ull* stp = st + j * 8;

    for (int t = 0; t < NSTEP; ++t) {
        // fill prev-feature tile
        for (int idx = j; idx < 32 * BM2; idx += NT2) {
            int kp = idx >> 4, r = idx & 15;
            float v = 0.f;
            if (t > 0 && kp < 29) v = target[((b0 + r) * NSTEP + (t - 1)) * 29 + kp];
            pd[kp * HDP + r] = v;
        }
        __syncthreads();   // pd ready; prior step's hd reads all complete

        ull aR[8] = {}, aZ[8] = {}, aN[8] = {};

        // K=29 input part (n-gate partial stashed separately)
        #pragma unroll 1
        for (int kp = 0; kp < 29; ++kp) {
            const float* wb = Wih + (260 + kp) * H3 + j;
            float wr = __ldcg(wb), wz = __ldcg(wb + 256), wn = __ldcg(wb + 512);
            ull wrd = dup2(wr), wzd = dup2(wz), wnd = dup2(wn);
            const ull* pp = (const ull*)(pd + kp * HDP);
            #pragma unroll
            for (int i = 0; i < 8; ++i) {
                ull p = pp[i];
                ffma2(aR[i], p, wrd);
                ffma2(aZ[i], p, wzd);
                ffma2(aN[i], p, wnd);
            }
        }
        #pragma unroll
        for (int i = 0; i < 8; ++i) { stp[i] = aN[i]; aN[i] = 0; }

        // main K=256 recurrent GEMM, depth-2 W register prefetch
        {
            const float* w0p = Whh + j;
            float wrA = __ldcg(w0p),       wzA = __ldcg(w0p + 256),       wnA = __ldcg(w0p + 512);
            float wrB = __ldcg(w0p + H3),  wzB = __ldcg(w0p + H3 + 256),  wnB = __ldcg(w0p + H3 + 512);
            #pragma unroll 4
            for (int k = 0; k < 256; ++k) {
                float wrN = 0.f, wzN = 0.f, wnN = 0.f;
                if (k + 2 < 256) {
                    const float* wb = Whh + (k + 2) * H3 + j;
                    wrN = __ldcg(wb); wzN = __ldcg(wb + 256); wnN = __ldcg(wb + 512);
                }
                ull wrd = dup2(wrA), wzd = dup2(wzA), wnd = dup2(wnA);
                const ull* hp = (const ull*)(hd + k * HDP);
                #pragma unroll
                for (int i = 0; i < 8; ++i) {
                    ull hv = hp[i];
                    ffma2(aR[i], hv, wrd);
                    ffma2(aZ[i], hv, wzd);
                    ffma2(aN[i], hv, wnd);
                }
                wrA = wrB; wzA = wzB; wnA = wnB;
                wrB = wrN; wzB = wzN; wnB = wnN;
            }
        }
        __syncthreads();   // all hd reads done before in-place update

        // gates + in-place h update (thread j owns column j)
        #pragma unroll
        for (int i = 0; i < 8; ++i) {
            float2 vR = unpk(aR[i]), vZ = unpk(aZ[i]);
            float2 vN = unpk(aN[i]), vI = unpk(stp[i]);
            int r0 = 2 * i, r1 = 2 * i + 1;
            const float* gz0 = g_gz + (b0 + r0) * H3 + j;
            const float* gz1 = g_gz + (b0 + r1) * H3 + j;
            float rg0 = sigf(vR.x + gz0[0]   + bhr);
            float rg1 = sigf(vR.y + gz1[0]   + bhr);
            float zg0 = sigf(vZ.x + gz0[256] + bhz);
            float zg1 = sigf(vZ.y + gz1[256] + bhz);
            float n0 = tanhf_fast(vI.x + gz0[512] + rg0 * (vN.x + bhn));
            float n1 = tanhf_fast(vI.y + gz1[512] + rg1 * (vN.y + bhn));
            float h0 = hd[j * HDP + r0], h1 = hd[j * HDP + r1];
            float hn0 = n0 + zg0 * (h0 - n0);
            float hn1 = n1 + zg1 * (h1 - n1);
            hd[j * HDP + r0] = hn0;
            hd[j * HDP + r1] = hn1;
            if (t == NSTEP - 1) {
                g_hA[(b0 + r0) * 256 + j] = hn0;
                g_hA[(b0 + r1) * 256 + j] = hn1;
            }
        }
        __syncthreads();   // new h visible before heads

        // heads: 15 type logits + 14 sigmoid params per row
        for (int idx = j; idx < BM2 * 29; idx += NT2) {
            int row = idx / 29, o = idx % 29;
            if (o < 15) {
                float acc = bt[o];
                #pragma unroll 8
                for (int k = 0; k < 256; ++k)
                    acc = fmaf(hd[k * HDP + row], Wt[k * 15 + o], acc);
                out1[((b0 + row) * NSTEP + t) * 15 + o] = acc;
            } else {
                int oo = o - 15;
                float acc = bp[oo];
                #pragma unroll 8
                for (int k = 0; k < 256; ++k)
                    acc = fmaf(hd[k * HDP + row], Wp[k * 14 + oo], acc);
                out2[((b0 + row) * NSTEP + t) * 14 + oo] = sigf(acc);
            }
        }
        // next iter's pd fill is ordered by the top-of-loop __syncthreads
    }
}

// ---------------------------------------------------------------------------
// Kernel 3: edge head. Every ordered pair uses the SAME MLP([h,h,zc]) value,
// so compute one scalar per row and broadcast to all 2450 slots.
// ---------------------------------------------------------------------------
__global__ void __launch_bounds__(NTHR) edge_kernel(
    const float* __restrict__ z,   const float* __restrict__ cond,
    const float* __restrict__ We1, const float* __restrict__ be1,
    const float* __restrict__ We2, const float* __restrict__ be2,
    float* __restrict__ out3)
{
    extern __shared__ float smf[];
    float* xT  = smf;               // [516][PAD]  (h 0..255, zc 256..515)
    float* e1T = xT + 516 * PAD;    // [256][PAD]
    float* ev  = e1T + 256 * PAD;   // [32]
    const int b0  = blockIdx.x * BM;
    const int tid = threadIdx.x;

    for (int idx = tid; idx < BM * 516; idx += NTHR) {
        int k = idx % 516, r = idx / 516;
        float v = (k < 256) ? g_hA[(b0 + r) * 256 + k]
                : (k < 512) ? z[(b0 + r) * 256 + (k - 256)]
                            : cond[(b0 + r) * 4 + (k - 512)];
        xT[k * PAD + r] = v;
    }
    __syncthreads();

    const int jp = tid & 127, rg = tid >> 7;
    const int j0 = jp * 2, r0 = rg * 8;

    ull acc[4][2] = {};
    #pragma unroll 2
    for (int k = 0; k < 772; ++k) {
        int xrow = (k < 512) ? (k & 255) : (k - 256);
        float2 w = *(const float2*)(We1 + k * H + j0);
        ull w0 = dup2(w.x), w1 = dup2(w.y);
        const float* xr = xT + xrow * PAD + r0;
        ull x01 = *(const ull*)(xr);
        ull x23 = *(const ull*)(xr + 2);
        ull x45 = *(const ull*)(xr + 4);
        ull x67 = *(const ull*)(xr + 6);
        ffma2(acc[0][0], x01, w0); ffma2(acc[0][1], x01, w1);
        ffma2(acc[1][0], x23, w0); ffma2(acc[1][1], x23, w1);
        ffma2(acc[2][0], x45, w0); ffma2(acc[2][1], x45, w1);
        ffma2(acc[3][0], x67, w0); ffma2(acc[3][1], x67, w1);
    }
    float bv0 = be1[j0], bv1 = be1[j0 + 1];
    #pragma unroll
    for (int p = 0; p < 4; ++p) {
        float2 a0 = unpk(acc[p][0]), a1 = unpk(acc[p][1]);
        int r = r0 + 2 * p;
        e1T[(j0    ) * PAD + r    ] = fmaxf(a0.x + bv0, 0.f);
        e1T[(j0    ) * PAD + r + 1] = fmaxf(a0.y + bv0, 0.f);
        e1T[(j0 + 1) * PAD + r    ] = fmaxf(a1.x + bv1, 0.f);
        e1T[(j0 + 1) * PAD + r + 1] = fmaxf(a1.y + bv1, 0.f);
    }
    __syncthreads();

    if (tid < BM) {
        float a = be2[0];
        #pragma unroll 8
        for (int k = 0; k < 256; ++k)
            a = fmaf(e1T[k * PAD + tid], We2[k], a);
        ev[tid] = a;
    }
    __syncthreads();

    for (int idx = tid; idx < BM * 2450; idx += NTHR) {
        int row = idx / 2450, col = idx % 2450;
        out3[(b0 + row) * 2450 + col] = ev[row];
    }
}

// ---------------------------------------------------------------------------
extern "C" void kernel_launch(void* const* d_in, const int* in_sizes, int n_in,
                              void* d_out, int out_size)
{
    (void)in_sizes; (void)n_in; (void)out_size;
    const float* z    = (const float*)d_in[0];
    const float* cond = (const float*)d_in[1];
    const float* tgt  = (const float*)d_in[2];
    const float* Wn1  = (const float*)d_in[3];
    const float* bn1  = (const float*)d_in[4];
    const float* Wn2  = (const float*)d_in[5];
    const float* bn2  = (const float*)d_in[6];
    const float* Wi   = (const float*)d_in[7];
    const float* bi   = (const float*)d_in[8];
    const float* Wih  = (const float*)d_in[9];
    const float* Whh  = (const float*)d_in[10];
    const float* bih  = (const float*)d_in[11];
    const float* bhh  = (const float*)d_in[12];
    const float* Wt   = (const float*)d_in[13];
    const float* bt   = (const float*)d_in[14];
    const float* Wp   = (const float*)d_in[15];
    const float* bp   = (const float*)d_in[16];
    const float* We1  = (const float*)d_in[17];
    const float* be1  = (const float*)d_in[18];
    const float* We2  = (const float*)d_in[19];
    const float* be2  = (const float*)d_in[20];

    float* out  = (float*)d_out;
    float* out0 = out;                                  // [B, 49]
    float* out1 = out0 + (size_t)B_SZ * 49;             // [B, 50, 15]
    float* out2 = out1 + (size_t)B_SZ * NSTEP * 15;     // [B, 50, 14]
    float* out3 = out2 + (size_t)B_SZ * NSTEP * 14;     // [B, 2450]

    const int PRE_SMEM  = (260 + 256) * PAD * 4;              // 74,304 B
    const int EDGE_SMEM = (516 + 256) * PAD * 4 + BM * 4;     // 111,296 B

    cudaFuncSetAttribute(pre_kernel,  cudaFuncAttributeMaxDynamicSharedMemorySize, PRE_SMEM);
    cudaFuncSetAttribute(edge_kernel, cudaFuncAttributeMaxDynamicSharedMemorySize, EDGE_SMEM);

    pre_kernel<<<B_SZ / BM, NTHR, PRE_SMEM>>>(z, cond, Wn1, bn1, Wn2, bn2, Wi, bi, Wih, bih, out0);
    gru_kernel<<<B_SZ / BM2, NT2>>>(tgt, Wih, Whh, bhh, Wt, bt, Wp, bp, out1, out2);
    edge_kernel<<<B_SZ / BM, NTHR, EDGE_SMEM>>>(z, cond, We1, be1, We2, be2, out3);
}